// round 14
// baseline (speedup 1.0000x reference)
#include <cuda_runtime.h>
#include <cuda_fp16.h>

typedef unsigned int uint;

#define N_NODES 50000
#define N_EDGES 800000
#define N_GRAPHS 64
#define EMB_DIM 128
#define IMG_DIM 4096
#define N_TYPES 30
#define CAT_DIM (IMG_DIM + EMB_DIM)   // 4224

#define IMG_SPLITS 8
#define IMG_KC 512                    // 4096/8
#define IMG_NTILES 32                 // 4096/128
#define IMG_BLOCKS (IMG_SPLITS * IMG_NTILES)  // 256
#define HEAD_KC 128
#define HI_SPLITS 32
#define HC_SPLITS 33
#define AGG_BLOCKS ((N_NODES + 7) / 8)
#define IRED_BLOCKS (64 * IMG_DIM / 256)      // 1024
#define TBL_BLOCKS 15
#define W23_BLOCKS 16                 // W2+W3 fp32->half (8192 float4)

// ---------------- device scratch (zero-initialized at module load; -------------
// ---------------- re-zeroed at the END of each run by k_headnorm) --------------
__device__ float g_degsum[N_NODES];           // accumulated edge weights (starts 0)
__device__ int   g_cnt_e[N_NODES];            // edge counts (starts 0)
__device__ int   g_cursor[N_NODES];           // scatter cursors (starts 0)
__device__ float g_dis[N_NODES];
__device__ int   g_offs[N_NODES + 1];
__device__ int2  g_epack[N_EDGES];            // (row, coef) for layers 2/3
__device__ int2  g_tpack[N_EDGES];            // (type[row], coef) for layer 1
__device__ int   g_goff[N_GRAPHS + 1];

__device__ __half g_XWh[N_NODES * EMB_DIM];   // node GEMM out / agg in (half)
__device__ __half g_bufAh[N_NODES * EMB_DIM]; // agg1 out (half, relu)
__device__ __half g_bufBh[N_NODES * EMB_DIM]; // agg2 out (half, relu)
__device__ float  g_bufC[N_NODES * EMB_DIM];  // agg3 out (fp32)
__device__ float  g_TXWf[N_TYPES * EMB_DIM];  // layer-1 table (fp32)
__device__ __half g_W2h[EMB_DIM * EMB_DIM];
__device__ __half g_W3h[EMB_DIM * EMB_DIM];
__device__ float  g_xc[N_GRAPHS * CAT_DIM];   // [xi | pooled]
__device__ float  g_ipart[IMG_SPLITS * 64 * IMG_DIM];
__device__ float  g_hpi[HI_SPLITS * 64 * EMB_DIM];
__device__ float  g_hpc[HC_SPLITS * 64 * EMB_DIM];

// ---------------- mega preprocessing kernel --------------------------------------
// blocks [0, nb_edges): edge deg/cnt atomics + graph boundaries
// blocks [nb_edges, +15): layer-1 table GEMM (TXW = emb @ W1^T, fp32 out)
// blocks [+15, +31): W2/W3 fp32 -> half
__global__ void k_deg(const int* __restrict__ ei, const float* __restrict__ ea,
                      const int* __restrict__ batch,
                      const float* __restrict__ emb, const float* __restrict__ W1,
                      const float* __restrict__ W2, const float* __restrict__ W3,
                      int nb_edges) {
    int bx = blockIdx.x;
    if (bx < nb_edges) {
        int i = bx * blockDim.x + threadIdx.x;
        if (i < N_EDGES) {
            int c = ei[N_EDGES + i];
            atomicAdd(&g_degsum[c], ea[i]);
            atomicAdd(&g_cnt_e[c], 1);
        }
        if (i < N_NODES) {
            int b = batch[i];
            if (i == 0) {
                for (int g = 0; g <= b; g++) g_goff[g] = 0;
            } else {
                int pb = batch[i - 1];
                for (int g = pb + 1; g <= b; g++) g_goff[g] = i;
            }
            if (i == N_NODES - 1)
                for (int g = b + 1; g <= N_GRAPHS; g++) g_goff[g] = N_NODES;
        }
    } else if (bx < nb_edges + TBL_BLOCKS) {
        __shared__ float xr[2][EMB_DIM];
        int blk = bx - nb_edges;
        int sub = threadIdx.x >> 7;
        int d = threadIdx.x & 127;
        int t = blk * 2 + sub;
        xr[sub][d] = emb[t * EMB_DIM + d];
        __syncthreads();
        const float* w = &W1[d * EMB_DIM];
        const float* x = xr[sub];
        float s = 0.f;
        #pragma unroll 8
        for (int k = 0; k < EMB_DIM; k++) s += x[k] * w[k];
        g_TXWf[t * EMB_DIM + d] = s;
    } else {
        int j = (bx - nb_edges - TBL_BLOCKS) * 256 + threadIdx.x;   // 0..4095
        #pragma unroll
        for (int q = 0; q < 2; q++) {
            int idx = j + q * 4096;
            const float* src = (idx < 4096) ? W2 : W3;
            __half* dst = (idx < 4096) ? g_W2h : g_W3h;
            int p = idx & 4095;
            float4 v = ((const float4*)src)[p];
            __half2* dd = (__half2*)(dst + (size_t)p * 4);
            dd[0] = __floats2half2_rn(v.x, v.y);
            dd[1] = __floats2half2_rn(v.z, v.w);
        }
    }
}

__global__ void k_scan() {
    __shared__ int sh[1024];
    const int C = (N_NODES + 1023) / 1024;
    int t = threadIdx.x;
    int base = t * C;
    int sum = 0;
    for (int j = 0; j < C; j++) { int i = base + j; if (i < N_NODES) sum += g_cnt_e[i]; }
    sh[t] = sum;
    __syncthreads();
    for (int off = 1; off < 1024; off <<= 1) {
        int v = (t >= off) ? sh[t - off] : 0;
        __syncthreads();
        sh[t] += v;
        __syncthreads();
    }
    int prefix = t ? sh[t - 1] : 0;
    for (int j = 0; j < C; j++) {
        int i = base + j;
        if (i < N_NODES) { int c = g_cnt_e[i]; g_offs[i] = prefix; prefix += c; }
    }
    if (t == 1023) g_offs[N_NODES] = sh[1023];
    for (int i = t; i < N_NODES; i += 1024)
        g_dis[i] = rsqrtf(1.0f + g_degsum[i]);
}

// ---------------- HMMA GEMM building block ---------------------------------------
__device__ __forceinline__ void mma16816(float* c, uint a0, uint a1, uint a2, uint a3,
                                         uint b0, uint b1) {
    asm volatile("mma.sync.aligned.m16n8k16.row.col.f32.f16.f16.f32 "
                 "{%0,%1,%2,%3}, {%4,%5,%6,%7}, {%8,%9}, {%0,%1,%2,%3};"
                 : "+f"(c[0]), "+f"(c[1]), "+f"(c[2]), "+f"(c[3])
                 : "r"(a0), "r"(a1), "r"(a2), "r"(a3), "r"(b0), "r"(b1));
}

// block tile 64(M) x 128(N), k-chunk 64; 8 warps = 4(M) x 2(N).
// Register double-buffered global loads. A/B each fp32 (CONV) or half.
template <bool CONV_A, bool CONV_B, bool OUT_HALF>
__device__ __forceinline__ void hgemm(const void* Av, int lda,
                                      const void* Bv, int ldb,
                                      float* __restrict__ C, int ldc,
                                      __half* __restrict__ Ch,
                                      int m0, int n0, int k0, int klen, int M) {
    __shared__ __half As[64][72];
    __shared__ __half Bs[128][72];
    int t = threadIdx.x;
    int w = t >> 5, l = t & 31;
    int g = l >> 2, tig = l & 3;
    int m_off = (w & 3) * 16, n_off = (w >> 2) * 64;

    float acc[8][4];
    #pragma unroll
    for (int nf = 0; nf < 8; nf++)
        #pragma unroll
        for (int j = 0; j < 4; j++) acc[nf][j] = 0.f;

    float4 raf[4];
    uint4  rah[2];
    float4 rbf[8];
    uint4  rbh[4];

    const int nk = klen >> 6;

    {
        int kc = k0;
        if (CONV_A) {
            const float* A = (const float*)Av;
            #pragma unroll
            for (int i = 0; i < 4; i++) {
                int idx = t + i * 256;
                int r = idx >> 4, c4 = (idx & 15) << 2;
                int am = m0 + r;
                raf[i] = (am < M) ? *(const float4*)&A[(size_t)am * lda + kc + c4]
                                  : make_float4(0.f, 0.f, 0.f, 0.f);
            }
        } else {
            const __half* A = (const __half*)Av;
            #pragma unroll
            for (int i = 0; i < 2; i++) {
                int idx = t + i * 256;
                int r = idx >> 3, c8 = (idx & 7) << 3;
                int am = m0 + r;
                rah[i] = (am < M) ? *(const uint4*)&A[(size_t)am * lda + kc + c8]
                                  : make_uint4(0u, 0u, 0u, 0u);
            }
        }
        if (CONV_B) {
            const float* B = (const float*)Bv;
            #pragma unroll
            for (int i = 0; i < 8; i++) {
                int idx = t + i * 256;
                int r = idx >> 4, c4 = (idx & 15) << 2;
                rbf[i] = *(const float4*)&B[(size_t)(n0 + r) * ldb + kc + c4];
            }
        } else {
            const __half* B = (const __half*)Bv;
            #pragma unroll
            for (int i = 0; i < 4; i++) {
                int idx = t + i * 256;
                int r = idx >> 3, c8 = (idx & 7) << 3;
                rbh[i] = *(const uint4*)&B[(size_t)(n0 + r) * ldb + kc + c8];
            }
        }
    }

    for (int it = 0; it < nk; it++) {
        if (CONV_A) {
            #pragma unroll
            for (int i = 0; i < 4; i++) {
                int idx = t + i * 256;
                int r = idx >> 4, c4 = (idx & 15) << 2;
                __half2* d = (__half2*)&As[r][c4];
                d[0] = __floats2half2_rn(raf[i].x, raf[i].y);
                d[1] = __floats2half2_rn(raf[i].z, raf[i].w);
            }
        } else {
            #pragma unroll
            for (int i = 0; i < 2; i++) {
                int idx = t + i * 256;
                int r = idx >> 3, c8 = (idx & 7) << 3;
                *(uint4*)&As[r][c8] = rah[i];
            }
        }
        if (CONV_B) {
            #pragma unroll
            for (int i = 0; i < 8; i++) {
                int idx = t + i * 256;
                int r = idx >> 4, c4 = (idx & 15) << 2;
                __half2* d = (__half2*)&Bs[r][c4];
                d[0] = __floats2half2_rn(rbf[i].x, rbf[i].y);
                d[1] = __floats2half2_rn(rbf[i].z, rbf[i].w);
            }
        } else {
            #pragma unroll
            for (int i = 0; i < 4; i++) {
                int idx = t + i * 256;
                int r = idx >> 3, c8 = (idx & 7) << 3;
                *(uint4*)&Bs[r][c8] = rbh[i];
            }
        }
        __syncthreads();

        if (it + 1 < nk) {
            int kc = k0 + (it + 1) * 64;
            if (CONV_A) {
                const float* A = (const float*)Av;
                #pragma unroll
                for (int i = 0; i < 4; i++) {
                    int idx = t + i * 256;
                    int r = idx >> 4, c4 = (idx & 15) << 2;
                    int am = m0 + r;
                    raf[i] = (am < M) ? *(const float4*)&A[(size_t)am * lda + kc + c4]
                                      : make_float4(0.f, 0.f, 0.f, 0.f);
                }
            } else {
                const __half* A = (const __half*)Av;
                #pragma unroll
                for (int i = 0; i < 2; i++) {
                    int idx = t + i * 256;
                    int r = idx >> 3, c8 = (idx & 7) << 3;
                    int am = m0 + r;
                    rah[i] = (am < M) ? *(const uint4*)&A[(size_t)am * lda + kc + c8]
                                      : make_uint4(0u, 0u, 0u, 0u);
                }
            }
            if (CONV_B) {
                const float* B = (const float*)Bv;
                #pragma unroll
                for (int i = 0; i < 8; i++) {
                    int idx = t + i * 256;
                    int r = idx >> 4, c4 = (idx & 15) << 2;
                    rbf[i] = *(const float4*)&B[(size_t)(n0 + r) * ldb + kc + c4];
                }
            } else {
                const __half* B = (const __half*)Bv;
                #pragma unroll
                for (int i = 0; i < 4; i++) {
                    int idx = t + i * 256;
                    int r = idx >> 3, c8 = (idx & 7) << 3;
                    rbh[i] = *(const uint4*)&B[(size_t)(n0 + r) * ldb + kc + c8];
                }
            }
        }

        #pragma unroll
        for (int ks = 0; ks < 4; ks++) {
            int kk = ks * 16 + 2 * tig;
            uint a0 = *(const uint*)&As[m_off + g][kk];
            uint a1 = *(const uint*)&As[m_off + g + 8][kk];
            uint a2 = *(const uint*)&As[m_off + g][kk + 8];
            uint a3 = *(const uint*)&As[m_off + g + 8][kk + 8];
            #pragma unroll
            for (int nf = 0; nf < 8; nf++) {
                uint b0 = *(const uint*)&Bs[n_off + nf * 8 + g][kk];
                uint b1 = *(const uint*)&Bs[n_off + nf * 8 + g][kk + 8];
                mma16816(acc[nf], a0, a1, a2, a3, b0, b1);
            }
        }
        __syncthreads();
    }

    #pragma unroll
    for (int nf = 0; nf < 8; nf++) {
        int col = n0 + n_off + nf * 8 + 2 * tig;
        int m1 = m0 + m_off + g, m2 = m1 + 8;
        if (OUT_HALF) {
            if (m1 < M) *(__half2*)&Ch[(size_t)m1 * EMB_DIM + col] = __floats2half2_rn(acc[nf][0], acc[nf][1]);
            if (m2 < M) *(__half2*)&Ch[(size_t)m2 * EMB_DIM + col] = __floats2half2_rn(acc[nf][2], acc[nf][3]);
        } else {
            if (m1 < M) { C[(size_t)m1 * ldc + col] = acc[nf][0]; C[(size_t)m1 * ldc + col + 1] = acc[nf][1]; }
            if (m2 < M) { C[(size_t)m2 * ldc + col] = acc[nf][2]; C[(size_t)m2 * ldc + col + 1] = acc[nf][3]; }
        }
    }
}

// ---------------- big fused kernel: image HMMA GEMM + edge scatter ---------------
__global__ void __launch_bounds__(256) k_big(const float* __restrict__ images,
                                             const float* __restrict__ W_img,
                                             const int* __restrict__ ei,
                                             const float* __restrict__ ea,
                                             const int* __restrict__ types) {
    if (blockIdx.x < IMG_BLOCKS) {
        int ntile = blockIdx.x & (IMG_NTILES - 1), z = blockIdx.x / IMG_NTILES;
        hgemm<true, true, false>(images, IMG_DIM, W_img, IMG_DIM,
                                 g_ipart + (size_t)z * 64 * IMG_DIM, IMG_DIM, nullptr,
                                 0, ntile * 128, z * IMG_KC, IMG_KC, 64);
    } else {
        int e = (blockIdx.x - IMG_BLOCKS) * 256 + threadIdx.x;
        if (e < N_EDGES) {
            int r = ei[e], c = ei[N_EDGES + e];
            float coef = g_dis[r] * ea[e] * g_dis[c];
            int pos = g_offs[c] + atomicAdd(&g_cursor[c], 1);
            int ci = __float_as_int(coef);
            g_epack[pos] = make_int2(r, ci);
            g_tpack[pos] = make_int2(types[r], ci);
        }
    }
}

// ---------------- layer-1 agg (fp32 smem table) + image reduce (fused) -----------
__global__ void __launch_bounds__(256) k_fused2(const float* __restrict__ b_img,
                                                const float* __restrict__ b1,
                                                const int* __restrict__ types) {
    if (blockIdx.x < IRED_BLOCKS) {
        int i = blockIdx.x * 256 + threadIdx.x;
        int m = i >> 12, n = i & (IMG_DIM - 1);
        float v = b_img[n];
        #pragma unroll
        for (int z = 0; z < IMG_SPLITS; z++)
            v += g_ipart[((size_t)z * 64 + m) * IMG_DIM + n];
        g_xc[m * CAT_DIM + n] = v;
        return;
    }
    // fp32 table in smem: N_TYPES x 128 floats = 15 KB; lane owns dims [lane*4, lane*4+4)
    __shared__ float4 sT[N_TYPES * 32];
    {
        const float4* src = (const float4*)g_TXWf;
        for (int i = threadIdx.x; i < N_TYPES * 32; i += 256)
            sT[i] = src[i];
    }
    __syncthreads();

    int bid = blockIdx.x - IRED_BLOCKS;
    int node = bid * 8 + ((int)threadIdx.x >> 5);
    if (node >= N_NODES) return;
    int lane = threadIdx.x & 31;
    int s = g_offs[node], e = g_offs[node + 1];
    float4 a0 = make_float4(0.f, 0.f, 0.f, 0.f);
    float4 a1 = make_float4(0.f, 0.f, 0.f, 0.f);
    int p = s;
    for (; p + 1 < e; p += 2) {
        int2 e0 = g_tpack[p], e1 = g_tpack[p + 1];
        float4 v0 = sT[e0.x * 32 + lane];
        float4 v1 = sT[e1.x * 32 + lane];
        float c0 = __int_as_float(e0.y), c1 = __int_as_float(e1.y);
        a0.x += c0 * v0.x; a0.y += c0 * v0.y; a0.z += c0 * v0.z; a0.w += c0 * v0.w;
        a1.x += c1 * v1.x; a1.y += c1 * v1.y; a1.z += c1 * v1.z; a1.w += c1 * v1.w;
    }
    if (p < e) {
        int2 e0 = g_tpack[p];
        float4 v0 = sT[e0.x * 32 + lane];
        float c0 = __int_as_float(e0.y);
        a0.x += c0 * v0.x; a0.y += c0 * v0.y; a0.z += c0 * v0.z; a0.w += c0 * v0.w;
    }
    a0.x += a1.x; a0.y += a1.y; a0.z += a1.z; a0.w += a1.w;
    float d2 = g_dis[node]; d2 *= d2;
    int ts = types[node];
    float4 sv = sT[ts * 32 + lane];
    float4 b = *(const float4*)&b1[lane * 4];
    a0.x += d2 * sv.x + b.x; a0.y += d2 * sv.y + b.y;
    a0.z += d2 * sv.z + b.z; a0.w += d2 * sv.w + b.w;
    a0.x = fmaxf(a0.x, 0.f); a0.y = fmaxf(a0.y, 0.f);
    a0.z = fmaxf(a0.z, 0.f); a0.w = fmaxf(a0.w, 0.f);
    __half2* dst = (__half2*)&g_bufAh[(size_t)node * EMB_DIM + lane * 4];
    dst[0] = __floats2half2_rn(a0.x, a0.y);
    dst[1] = __floats2half2_rn(a0.z, a0.w);
}

// ---------------- CSR aggregation layers 2/3 (half in) ---------------------------
template <bool RELU, bool OUT_H>
__global__ void __launch_bounds__(256) k_agg(const float* __restrict__ bias,
                                             __half* __restrict__ outh,
                                             float* __restrict__ outf) {
    int node = blockIdx.x * 8 + ((int)threadIdx.x >> 5);
    if (node >= N_NODES) return;
    int lane = threadIdx.x & 31;
    const __half2* xh = (const __half2*)g_XWh;
    int s = g_offs[node], e = g_offs[node + 1];
    float4 a0 = make_float4(0.f, 0.f, 0.f, 0.f);
    float4 a1 = make_float4(0.f, 0.f, 0.f, 0.f);
    int p = s;
    for (; p + 1 < e; p += 2) {
        int2 e0 = g_epack[p], e1 = g_epack[p + 1];
        uint2 r0 = *(const uint2*)(xh + (size_t)e0.x * 64 + lane * 2);
        uint2 r1 = *(const uint2*)(xh + (size_t)e1.x * 64 + lane * 2);
        float c0 = __int_as_float(e0.y), c1 = __int_as_float(e1.y);
        float2 f00 = __half22float2(*(__half2*)&r0.x), f01 = __half22float2(*(__half2*)&r0.y);
        float2 f10 = __half22float2(*(__half2*)&r1.x), f11 = __half22float2(*(__half2*)&r1.y);
        a0.x += c0 * f00.x; a0.y += c0 * f00.y; a0.z += c0 * f01.x; a0.w += c0 * f01.y;
        a1.x += c1 * f10.x; a1.y += c1 * f10.y; a1.z += c1 * f11.x; a1.w += c1 * f11.y;
    }
    if (p < e) {
        int2 e0 = g_epack[p];
        uint2 r0 = *(const uint2*)(xh + (size_t)e0.x * 64 + lane * 2);
        float c0 = __int_as_float(e0.y);
        float2 f00 = __half22float2(*(__half2*)&r0.x), f01 = __half22float2(*(__half2*)&r0.y);
        a0.x += c0 * f00.x; a0.y += c0 * f00.y; a0.z += c0 * f01.x; a0.w += c0 * f01.y;
    }
    a0.x += a1.x; a0.y += a1.y; a0.z += a1.z; a0.w += a1.w;
    float d2 = g_dis[node]; d2 *= d2;
    uint2 rv = *(const uint2*)(xh + (size_t)node * 64 + lane * 2);
    float2 v0 = __half22float2(*(__half2*)&rv.x), v1 = __half22float2(*(__half2*)&rv.y);
    float4 b = *(const float4*)&bias[lane * 4];
    a0.x += d2 * v0.x + b.x; a0.y += d2 * v0.y + b.y;
    a0.z += d2 * v1.x + b.z; a0.w += d2 * v1.y + b.w;
    if (RELU) {
        a0.x = fmaxf(a0.x, 0.f); a0.y = fmaxf(a0.y, 0.f);
        a0.z = fmaxf(a0.z, 0.f); a0.w = fmaxf(a0.w, 0.f);
    }
    if (OUT_H) {
        __half2* dst = (__half2*)&outh[(size_t)node * EMB_DIM + lane * 4];
        dst[0] = __floats2half2_rn(a0.x, a0.y);
        dst[1] = __floats2half2_rn(a0.z, a0.w);
    } else {
        *(float4*)&outf[(size_t)node * EMB_DIM + lane * 4] = a0;
    }
}

// node GEMM: [N_NODES,128](half) x W[128,128]^T(half) -> half g_XWh
__global__ void __launch_bounds__(256) k_hgemm_node(const __half* __restrict__ A,
                                                    const __half* __restrict__ Wh) {
    hgemm<false, false, true>(A, EMB_DIM, Wh, EMB_DIM, nullptr, 0, g_XWh,
                              blockIdx.y * 64, 0, 0, EMB_DIM, N_NODES);
}

__global__ void __launch_bounds__(512) k_pool_seg(const float* __restrict__ xg) {
    __shared__ float sh[512];
    int g = blockIdx.x;
    int d = threadIdx.x & 127, l4 = threadIdx.x >> 7;
    int s = g_goff[g], e = g_goff[g + 1];
    float acc = 0.f;
    for (int i = s + l4; i < e; i += 4) acc += xg[(size_t)i * EMB_DIM + d];
    sh[threadIdx.x] = acc;
    __syncthreads();
    if (threadIdx.x < 128) {
        float v = sh[d] + sh[128 + d] + sh[256 + d] + sh[384 + d];
        float c = fmaxf((float)(e - s), 1.f);
        g_xc[g * CAT_DIM + IMG_DIM + d] = v / c;
    }
}

// ---------------- fp32 SIMT 64x64 SGEMM (heads) ----------------------------------
__device__ __forceinline__ void sgemm64(const float* __restrict__ A, int lda,
                                        const float* __restrict__ B, int ldb,
                                        float* __restrict__ C, int ldc,
                                        int m0, int n0, int k0, int klen,
                                        int M, int N) {
    __shared__ float As[16][68];
    __shared__ float Bs[16][68];
    int t = threadIdx.x;
    int tn = t & 15, tm = t >> 4;
    int lrow = t >> 2, lkq = (t & 3) << 2;

    float c[4][4];
    #pragma unroll
    for (int i = 0; i < 4; i++)
        #pragma unroll
        for (int j = 0; j < 4; j++) c[i][j] = 0.f;

    for (int kk = k0; kk < k0 + klen; kk += 16) {
        float4 a;
        int am = m0 + lrow;
        if (am < M) a = *(const float4*)&A[(size_t)am * lda + kk + lkq];
        else        a = make_float4(0.f, 0.f, 0.f, 0.f);
        As[lkq + 0][lrow] = a.x; As[lkq + 1][lrow] = a.y;
        As[lkq + 2][lrow] = a.z; As[lkq + 3][lrow] = a.w;
        int bn = n0 + lrow;
        float4 b;
        if (bn < N) b = *(const float4*)&B[(size_t)bn * ldb + kk + lkq];
        else        b = make_float4(0.f, 0.f, 0.f, 0.f);
        Bs[lkq + 0][lrow] = b.x; Bs[lkq + 1][lrow] = b.y;
        Bs[lkq + 2][lrow] = b.z; Bs[lkq + 3][lrow] = b.w;
        __syncthreads();
        #pragma unroll
        for (int k = 0; k < 16; k++) {
            float4 af = *(const float4*)&As[k][tm * 4];
            float4 bf = *(const float4*)&Bs[k][tn * 4];
            c[0][0] += af.x * bf.x; c[0][1] += af.x * bf.y; c[0][2] += af.x * bf.z; c[0][3] += af.x * bf.w;
            c[1][0] += af.y * bf.x; c[1][1] += af.y * bf.y; c[1][2] += af.y * bf.z; c[1][3] += af.y * bf.w;
            c[2][0] += af.z * bf.x; c[2][1] += af.z * bf.y; c[2][2] += af.z * bf.z; c[2][3] += af.z * bf.w;
            c[3][0] += af.w * bf.x; c[3][1] += af.w * bf.y; c[3][2] += af.w * bf.z; c[3][3] += af.w * bf.w;
        }
        __syncthreads();
    }
    #pragma unroll
    for (int i = 0; i < 4; i++) {
        int m = m0 + tm * 4 + i;
        if (m >= M) continue;
        #pragma unroll
        for (int j = 0; j < 4; j++)
            C[(size_t)m * ldc + n0 + tn * 4 + j] = c[i][j];
    }
}

// both heads, one launch: z<HI_SPLITS -> oi partials, else oc partials
__global__ void __launch_bounds__(256) k_heads(const float* __restrict__ xc,
                                               const float* __restrict__ Wi,
                                               const float* __restrict__ Wc) {
    int z = blockIdx.z;
    if (z < HI_SPLITS) {
        sgemm64(xc, CAT_DIM, Wi, IMG_DIM, g_hpi + (size_t)z * 64 * EMB_DIM, EMB_DIM,
                0, blockIdx.x * 64, z * HEAD_KC, HEAD_KC, 64, EMB_DIM);
    } else {
        int z2 = z - HI_SPLITS;
        sgemm64(xc, CAT_DIM, Wc, CAT_DIM, g_hpc + (size_t)z2 * 64 * EMB_DIM, EMB_DIM,
                0, blockIdx.x * 64, z2 * HEAD_KC, HEAD_KC, 64, EMB_DIM);
    }
}

// reduce + normalize + re-zero accumulators for the NEXT run
__global__ void k_headnorm(const float* __restrict__ bi, const float* __restrict__ bc,
                           float* __restrict__ out) {
    __shared__ float sh[4];
    int which = blockIdx.x >> 6, m = blockIdx.x & 63, n = threadIdx.x;
    float v;
    if (which == 0) {
        v = bi[n];
        #pragma unroll
        for (int z = 0; z < HI_SPLITS; z++) v += g_hpi[(z * 64 + m) * EMB_DIM + n];
    } else {
        v = bc[n];
        #pragma unroll
        for (int z = 0; z < HC_SPLITS; z++) v += g_hpc[(z * 64 + m) * EMB_DIM + n];
    }
    float s = v * v;
    #pragma unroll
    for (int o = 16; o; o >>= 1) s += __shfl_xor_sync(0xffffffffu, s, o);
    if ((n & 31) == 0) sh[n >> 5] = s;
    __syncthreads();
    float tot = sh[0] + sh[1] + sh[2] + sh[3];
    out[blockIdx.x * EMB_DIM + n] = v * rsqrtf(tot);

    // cleanup: zero the atomically-accumulated state for the next replay.
    int tid = blockIdx.x * EMB_DIM + threadIdx.x;
    for (int i = tid; i < N_NODES; i += 128 * EMB_DIM) {
        g_degsum[i] = 0.f;
        g_cnt_e[i] = 0;
        g_cursor[i] = 0;
    }
}

// ---------------- host ----------------------------------------------------------
extern "C" void kernel_launch(void* const* d_in, const int* in_sizes, int n_in,
                              void* d_out, int out_size) {
    const float* images = (const float*)d_in[0];
    const int*   ntypes = (const int*)  d_in[1];
    const int*   eidx   = (const int*)  d_in[2];
    const float* eattr  = (const float*)d_in[3];
    const int*   batch  = (const int*)  d_in[4];
    const float* emb    = (const float*)d_in[5];
    const float* W_img  = (const float*)d_in[6];
    const float* b_img  = (const float*)d_in[7];
    const float* W1     = (const float*)d_in[8];
    const float* b1     = (const float*)d_in[9];
    const float* W2     = (const float*)d_in[10];
    const float* b2     = (const float*)d_in[11];
    const float* W3     = (const float*)d_in[12];
    const float* b3     = (const float*)d_in[13];
    const float* Wi     = (const float*)d_in[14];
    const float* bi     = (const float*)d_in[15];
    const float* Wc     = (const float*)d_in[16];
    const float* bc     = (const float*)d_in[17];
    float* out = (float*)d_out;

    __half *p_bufAh, *p_bufBh, *p_W2h, *p_W3h;
    float *p_bufC, *p_xc;
    cudaGetSymbolAddress((void**)&p_bufAh, g_bufAh);
    cudaGetSymbolAddress((void**)&p_bufBh, g_bufBh);
    cudaGetSymbolAddress((void**)&p_W2h,   g_W2h);
    cudaGetSymbolAddress((void**)&p_W3h,   g_W3h);
    cudaGetSymbolAddress((void**)&p_bufC,  g_bufC);
    cudaGetSymbolAddress((void**)&p_xc,    g_xc);

    const int T = 256;
    int nb_edges = (N_EDGES + T - 1) / T;

    // preprocessing: deg/cnt atomics + boundaries + table GEMM + W2/W3 -> half
    k_deg<<<nb_edges + TBL_BLOCKS + W23_BLOCKS, T>>>(eidx, eattr, batch,
                                                     emb, W1, W2, W3, nb_edges);
    k_scan<<<1, 1024>>>();

    // image GEMM (pipelined) + edge scatter in one launch
    k_big<<<IMG_BLOCKS + nb_edges, T>>>(images, W_img, eidx, eattr, ntypes);

    // image reduce + layer-1 agg (fp32 smem table) in one launch
    k_fused2<<<IRED_BLOCKS + AGG_BLOCKS, T>>>(b_img, b1, ntypes);

    // layer 2 (HMMA, half x half) + agg
    k_hgemm_node<<<dim3(1, (N_NODES + 63) / 64), T>>>(p_bufAh, p_W2h);
    k_agg<true, true><<<AGG_BLOCKS, T>>>(b2, p_bufBh, nullptr);

    // layer 3 (HMMA, half x half) + agg (fp32 out)
    k_hgemm_node<<<dim3(1, (N_NODES + 63) / 64), T>>>(p_bufBh, p_W3h);
    k_agg<false, false><<<AGG_BLOCKS, T>>>(b3, nullptr, p_bufC);

    // pooling -> g_xc[:, 4096:]
    k_pool_seg<<<N_GRAPHS, 512>>>(p_bufC);

    // heads (one launch) + fused reduce/normalize (+ state cleanup for next run)
    k_heads<<<dim3(2, 1, HI_SPLITS + HC_SPLITS), T>>>(p_xc, Wi, Wc);
    k_headnorm<<<2 * 64, EMB_DIM>>>(bi, bc, out);

    (void)in_sizes; (void)n_in; (void)out_size;
}

// round 15
// speedup vs baseline: 1.0367x; 1.0367x over previous
#include <cuda_runtime.h>
#include <cuda_fp16.h>

typedef unsigned int uint;

#define N_NODES 50000
#define N_EDGES 800000
#define N_GRAPHS 64
#define EMB_DIM 128
#define IMG_DIM 4096
#define N_TYPES 30
#define CAT_DIM (IMG_DIM + EMB_DIM)   // 4224

#define IMG_SPLITS 8
#define IMG_KC 512                    // 4096/8
#define IMG_NTILES 32                 // 4096/128
#define IMG_BLOCKS (IMG_SPLITS * IMG_NTILES)  // 256
#define HEAD_KC 128
#define HI_SPLITS 32
#define HC_SPLITS 33
#define AGG_BLOCKS ((N_NODES + 7) / 8)
#define IRED_BLOCKS (64 * IMG_DIM / 256)      // 1024

// ---------------- device scratch ------------------------------------------------
__device__ float g_dis[N_NODES];
__device__ int   g_cnt_e[N_NODES];
__device__ int   g_offs[N_NODES + 1];
__device__ int   g_cursor[N_NODES];
__device__ int2  g_epack[N_EDGES];            // (row, coef) for layers 2/3
__device__ int2  g_tpack[N_EDGES];            // (type[row], coef) for layer 1
__device__ int   g_goff[N_GRAPHS + 1];

__device__ __half g_XWh[N_NODES * EMB_DIM];   // node GEMM out / agg in (half)
__device__ __half g_bufAh[N_NODES * EMB_DIM]; // agg1 out (half, relu)
__device__ __half g_bufBh[N_NODES * EMB_DIM]; // agg2 out (half, relu)
__device__ float  g_bufC[N_NODES * EMB_DIM];  // agg3 out (fp32)
__device__ __half g_TXWh[N_TYPES * EMB_DIM];
__device__ float  g_xc[N_GRAPHS * CAT_DIM];   // [xi | pooled]
__device__ float  g_ipart[IMG_SPLITS * 64 * IMG_DIM];
__device__ float  g_hpi[HI_SPLITS * 64 * EMB_DIM];
__device__ float  g_hpc[HC_SPLITS * 64 * EMB_DIM];

// ---------------- init + layer-1 table GEMM (fused) -----------------------------
__global__ void k_init_table(const float* __restrict__ emb, const float* __restrict__ W1) {
    if (blockIdx.x < 15) {
        __shared__ float xr[2][EMB_DIM];
        int sub = threadIdx.x >> 7;
        int d = threadIdx.x & 127;
        int t = blockIdx.x * 2 + sub;
        xr[sub][d] = emb[t * EMB_DIM + d];
        __syncthreads();
        const float* w = &W1[d * EMB_DIM];
        const float* x = xr[sub];
        float s = 0.f;
        #pragma unroll 8
        for (int k = 0; k < EMB_DIM; k++) s += x[k] * w[k];
        g_TXWh[t * EMB_DIM + d] = __float2half(s);
    } else {
        int i = (blockIdx.x - 15) * blockDim.x + threadIdx.x;
        if (i < N_NODES) { g_dis[i] = 1.0f; g_cnt_e[i] = 0; g_cursor[i] = 0; }
    }
}

__global__ void k_deg(const int* __restrict__ ei, const float* __restrict__ ea,
                      const int* __restrict__ batch) {
    int i = blockIdx.x * blockDim.x + threadIdx.x;
    if (i < N_EDGES) {
        int c = ei[N_EDGES + i];
        atomicAdd(&g_dis[c], ea[i]);
        atomicAdd(&g_cnt_e[c], 1);
    }
    if (i < N_NODES) {
        int b = batch[i];
        if (i == 0) {
            for (int g = 0; g <= b; g++) g_goff[g] = 0;
        } else {
            int pb = batch[i - 1];
            for (int g = pb + 1; g <= b; g++) g_goff[g] = i;
        }
        if (i == N_NODES - 1)
            for (int g = b + 1; g <= N_GRAPHS; g++) g_goff[g] = N_NODES;
    }
}

__global__ void k_scan() {
    __shared__ int sh[1024];
    const int C = (N_NODES + 1023) / 1024;
    int t = threadIdx.x;
    int base = t * C;
    int sum = 0;
    for (int j = 0; j < C; j++) { int i = base + j; if (i < N_NODES) sum += g_cnt_e[i]; }
    sh[t] = sum;
    __syncthreads();
    for (int off = 1; off < 1024; off <<= 1) {
        int v = (t >= off) ? sh[t - off] : 0;
        __syncthreads();
        sh[t] += v;
        __syncthreads();
    }
    int prefix = t ? sh[t - 1] : 0;
    for (int j = 0; j < C; j++) {
        int i = base + j;
        if (i < N_NODES) { int c = g_cnt_e[i]; g_offs[i] = prefix; prefix += c; }
    }
    if (t == 1023) g_offs[N_NODES] = sh[1023];
    for (int i = t; i < N_NODES; i += 1024) g_dis[i] = rsqrtf(g_dis[i]);
}

// ---------------- HMMA GEMM building block ---------------------------------------
__device__ __forceinline__ void mma16816(float* c, uint a0, uint a1, uint a2, uint a3,
                                         uint b0, uint b1) {
    asm volatile("mma.sync.aligned.m16n8k16.row.col.f32.f16.f16.f32 "
                 "{%0,%1,%2,%3}, {%4,%5,%6,%7}, {%8,%9}, {%0,%1,%2,%3};"
                 : "+f"(c[0]), "+f"(c[1]), "+f"(c[2]), "+f"(c[3])
                 : "r"(a0), "r"(a1), "r"(a2), "r"(a3), "r"(b0), "r"(b1));
}

// block tile 64(M) x 128(N), k-chunk 64; 8 warps = 4(M) x 2(N).
// Register double-buffered global loads.
template <bool CONV_A, bool OUT_HALF>
__device__ __forceinline__ void hgemm(const void* Av, int lda,
                                      const float* __restrict__ B, int ldb,
                                      float* __restrict__ C, int ldc,
                                      __half* __restrict__ Ch,
                                      int m0, int n0, int k0, int klen, int M) {
    __shared__ __half As[64][72];
    __shared__ __half Bs[128][72];
    int t = threadIdx.x;
    int w = t >> 5, l = t & 31;
    int g = l >> 2, tig = l & 3;
    int m_off = (w & 3) * 16, n_off = (w >> 2) * 64;

    float acc[8][4];
    #pragma unroll
    for (int nf = 0; nf < 8; nf++)
        #pragma unroll
        for (int j = 0; j < 4; j++) acc[nf][j] = 0.f;

    float4 ra[4];
    uint4  rah[2];
    float4 rb[8];

    const int nk = klen >> 6;

    {
        int kc = k0;
        if (CONV_A) {
            const float* A = (const float*)Av;
            #pragma unroll
            for (int i = 0; i < 4; i++) {
                int idx = t + i * 256;
                int r = idx >> 4, c4 = (idx & 15) << 2;
                int am = m0 + r;
                ra[i] = (am < M) ? *(const float4*)&A[(size_t)am * lda + kc + c4]
                                 : make_float4(0.f, 0.f, 0.f, 0.f);
            }
        } else {
            const __half* A = (const __half*)Av;
            #pragma unroll
            for (int i = 0; i < 2; i++) {
                int idx = t + i * 256;
                int r = idx >> 3, c8 = (idx & 7) << 3;
                int am = m0 + r;
                rah[i] = (am < M) ? *(const uint4*)&A[(size_t)am * lda + kc + c8]
                                  : make_uint4(0u, 0u, 0u, 0u);
            }
        }
        #pragma unroll
        for (int i = 0; i < 8; i++) {
            int idx = t + i * 256;
            int r = idx >> 4, c4 = (idx & 15) << 2;
            rb[i] = *(const float4*)&B[(size_t)(n0 + r) * ldb + kc + c4];
        }
    }

    for (int it = 0; it < nk; it++) {
        if (CONV_A) {
            #pragma unroll
            for (int i = 0; i < 4; i++) {
                int idx = t + i * 256;
                int r = idx >> 4, c4 = (idx & 15) << 2;
                __half2* d = (__half2*)&As[r][c4];
                d[0] = __floats2half2_rn(ra[i].x, ra[i].y);
                d[1] = __floats2half2_rn(ra[i].z, ra[i].w);
            }
        } else {
            #pragma unroll
            for (int i = 0; i < 2; i++) {
                int idx = t + i * 256;
                int r = idx >> 3, c8 = (idx & 7) << 3;
                *(uint4*)&As[r][c8] = rah[i];
            }
        }
        #pragma unroll
        for (int i = 0; i < 8; i++) {
            int idx = t + i * 256;
            int r = idx >> 4, c4 = (idx & 15) << 2;
            __half2* d = (__half2*)&Bs[r][c4];
            d[0] = __floats2half2_rn(rb[i].x, rb[i].y);
            d[1] = __floats2half2_rn(rb[i].z, rb[i].w);
        }
        __syncthreads();

        if (it + 1 < nk) {
            int kc = k0 + (it + 1) * 64;
            if (CONV_A) {
                const float* A = (const float*)Av;
                #pragma unroll
                for (int i = 0; i < 4; i++) {
                    int idx = t + i * 256;
                    int r = idx >> 4, c4 = (idx & 15) << 2;
                    int am = m0 + r;
                    ra[i] = (am < M) ? *(const float4*)&A[(size_t)am * lda + kc + c4]
                                     : make_float4(0.f, 0.f, 0.f, 0.f);
                }
            } else {
                const __half* A = (const __half*)Av;
                #pragma unroll
                for (int i = 0; i < 2; i++) {
                    int idx = t + i * 256;
                    int r = idx >> 3, c8 = (idx & 7) << 3;
                    int am = m0 + r;
                    rah[i] = (am < M) ? *(const uint4*)&A[(size_t)am * lda + kc + c8]
                                      : make_uint4(0u, 0u, 0u, 0u);
                }
            }
            #pragma unroll
            for (int i = 0; i < 8; i++) {
                int idx = t + i * 256;
                int r = idx >> 4, c4 = (idx & 15) << 2;
                rb[i] = *(const float4*)&B[(size_t)(n0 + r) * ldb + kc + c4];
            }
        }

        #pragma unroll
        for (int ks = 0; ks < 4; ks++) {
            int kk = ks * 16 + 2 * tig;
            uint a0 = *(const uint*)&As[m_off + g][kk];
            uint a1 = *(const uint*)&As[m_off + g + 8][kk];
            uint a2 = *(const uint*)&As[m_off + g][kk + 8];
            uint a3 = *(const uint*)&As[m_off + g + 8][kk + 8];
            #pragma unroll
            for (int nf = 0; nf < 8; nf++) {
                uint b0 = *(const uint*)&Bs[n_off + nf * 8 + g][kk];
                uint b1 = *(const uint*)&Bs[n_off + nf * 8 + g][kk + 8];
                mma16816(acc[nf], a0, a1, a2, a3, b0, b1);
            }
        }
        __syncthreads();
    }

    #pragma unroll
    for (int nf = 0; nf < 8; nf++) {
        int col = n0 + n_off + nf * 8 + 2 * tig;
        int m1 = m0 + m_off + g, m2 = m1 + 8;
        if (OUT_HALF) {
            if (m1 < M) *(__half2*)&Ch[(size_t)m1 * EMB_DIM + col] = __floats2half2_rn(acc[nf][0], acc[nf][1]);
            if (m2 < M) *(__half2*)&Ch[(size_t)m2 * EMB_DIM + col] = __floats2half2_rn(acc[nf][2], acc[nf][3]);
        } else {
            if (m1 < M) { C[(size_t)m1 * ldc + col] = acc[nf][0]; C[(size_t)m1 * ldc + col + 1] = acc[nf][1]; }
            if (m2 < M) { C[(size_t)m2 * ldc + col] = acc[nf][2]; C[(size_t)m2 * ldc + col + 1] = acc[nf][3]; }
        }
    }
}

// ---------------- big fused kernel: image HMMA GEMM + edge scatter ---------------
__global__ void __launch_bounds__(256) k_big(const float* __restrict__ images,
                                             const float* __restrict__ W_img,
                                             const int* __restrict__ ei,
                                             const float* __restrict__ ea,
                                             const int* __restrict__ types) {
    if (blockIdx.x < IMG_BLOCKS) {
        int ntile = blockIdx.x & (IMG_NTILES - 1), z = blockIdx.x / IMG_NTILES;
        hgemm<true, false>(images, IMG_DIM, W_img, IMG_DIM,
                           g_ipart + (size_t)z * 64 * IMG_DIM, IMG_DIM, nullptr,
                           0, ntile * 128, z * IMG_KC, IMG_KC, 64);
    } else {
        int e = (blockIdx.x - IMG_BLOCKS) * 256 + threadIdx.x;
        if (e < N_EDGES) {
            int r = ei[e], c = ei[N_EDGES + e];
            float coef = g_dis[r] * ea[e] * g_dis[c];
            int pos = g_offs[c] + atomicAdd(&g_cursor[c], 1);
            int ci = __float_as_int(coef);
            g_epack[pos] = make_int2(r, ci);
            g_tpack[pos] = make_int2(types[r], ci);
        }
    }
}

// ---------------- layer-1 agg (half smem table, HFMA2) + image reduce ------------
__global__ void __launch_bounds__(256) k_fused2(const float* __restrict__ b_img,
                                                const float* __restrict__ b1,
                                                const int* __restrict__ types) {
    if (blockIdx.x < IRED_BLOCKS) {
        int i = blockIdx.x * 256 + threadIdx.x;
        int m = i >> 12, n = i & (IMG_DIM - 1);
        float v = b_img[n];
        #pragma unroll
        for (int z = 0; z < IMG_SPLITS; z++)
            v += g_ipart[((size_t)z * 64 + m) * IMG_DIM + n];
        g_xc[m * CAT_DIM + n] = v;
        return;
    }
    __shared__ uint sT[N_TYPES * 64];   // 30 rows x 64 half2
    for (int i = threadIdx.x; i < N_TYPES * 64; i += 256)
        sT[i] = ((const uint*)g_TXWh)[i];
    __syncthreads();

    int bid = blockIdx.x - IRED_BLOCKS;
    int node = bid * 8 + ((int)threadIdx.x >> 5);
    if (node >= N_NODES) return;
    int lane = threadIdx.x & 31;
    int s = g_offs[node], e = g_offs[node + 1];

    // half2 accumulators: two independent chains for ILP
    __half2 z2 = __floats2half2_rn(0.f, 0.f);
    __half2 a00 = z2, a01 = z2;   // chain 0: dims lane*4+0..1, +2..3
    __half2 a10 = z2, a11 = z2;   // chain 1
    int p = s;
    for (; p + 1 < e; p += 2) {
        int2 e0 = g_tpack[p], e1 = g_tpack[p + 1];
        uint2 r0 = *(const uint2*)&sT[e0.x * 64 + lane * 2];
        uint2 r1 = *(const uint2*)&sT[e1.x * 64 + lane * 2];
        __half2 c0 = __float2half2_rn(__int_as_float(e0.y));
        __half2 c1 = __float2half2_rn(__int_as_float(e1.y));
        a00 = __hfma2(*(__half2*)&r0.x, c0, a00);
        a01 = __hfma2(*(__half2*)&r0.y, c0, a01);
        a10 = __hfma2(*(__half2*)&r1.x, c1, a10);
        a11 = __hfma2(*(__half2*)&r1.y, c1, a11);
    }
    if (p < e) {
        int2 e0 = g_tpack[p];
        uint2 r0 = *(const uint2*)&sT[e0.x * 64 + lane * 2];
        __half2 c0 = __float2half2_rn(__int_as_float(e0.y));
        a00 = __hfma2(*(__half2*)&r0.x, c0, a00);
        a01 = __hfma2(*(__half2*)&r0.y, c0, a01);
    }
    // combine chains in fp32, add self-loop + bias, relu
    float2 f0 = __half22float2(a00), f0b = __half22float2(a10);
    float2 f1 = __half22float2(a01), f1b = __half22float2(a11);
    float4 acc = make_float4(f0.x + f0b.x, f0.y + f0b.y, f1.x + f1b.x, f1.y + f1b.y);
    float d2 = g_dis[node]; d2 *= d2;
    int ts = types[node];
    uint2 rv = *(const uint2*)&sT[ts * 64 + lane * 2];
    float2 v0 = __half22float2(*(__half2*)&rv.x), v1 = __half22float2(*(__half2*)&rv.y);
    float4 b = *(const float4*)&b1[lane * 4];
    acc.x += d2 * v0.x + b.x; acc.y += d2 * v0.y + b.y;
    acc.z += d2 * v1.x + b.z; acc.w += d2 * v1.y + b.w;
    acc.x = fmaxf(acc.x, 0.f); acc.y = fmaxf(acc.y, 0.f);
    acc.z = fmaxf(acc.z, 0.f); acc.w = fmaxf(acc.w, 0.f);
    __half2* dst = (__half2*)&g_bufAh[(size_t)node * EMB_DIM + lane * 4];
    dst[0] = __floats2half2_rn(acc.x, acc.y);
    dst[1] = __floats2half2_rn(acc.z, acc.w);
}

// ---------------- CSR aggregation layers 2/3 (half in) ---------------------------
template <bool RELU, bool OUT_H>
__global__ void __launch_bounds__(256) k_agg(const float* __restrict__ bias,
                                             __half* __restrict__ outh,
                                             float* __restrict__ outf) {
    int node = blockIdx.x * 8 + ((int)threadIdx.x >> 5);
    if (node >= N_NODES) return;
    int lane = threadIdx.x & 31;
    const __half2* xh = (const __half2*)g_XWh;
    int s = g_offs[node], e = g_offs[node + 1];
    float4 a0 = make_float4(0.f, 0.f, 0.f, 0.f);
    float4 a1 = make_float4(0.f, 0.f, 0.f, 0.f);
    int p = s;
    for (; p + 1 < e; p += 2) {
        int2 e0 = g_epack[p], e1 = g_epack[p + 1];
        uint2 r0 = *(const uint2*)(xh + (size_t)e0.x * 64 + lane * 2);
        uint2 r1 = *(const uint2*)(xh + (size_t)e1.x * 64 + lane * 2);
        float c0 = __int_as_float(e0.y), c1 = __int_as_float(e1.y);
        float2 f00 = __half22float2(*(__half2*)&r0.x), f01 = __half22float2(*(__half2*)&r0.y);
        float2 f10 = __half22float2(*(__half2*)&r1.x), f11 = __half22float2(*(__half2*)&r1.y);
        a0.x += c0 * f00.x; a0.y += c0 * f00.y; a0.z += c0 * f01.x; a0.w += c0 * f01.y;
        a1.x += c1 * f10.x; a1.y += c1 * f10.y; a1.z += c1 * f11.x; a1.w += c1 * f11.y;
    }
    if (p < e) {
        int2 e0 = g_epack[p];
        uint2 r0 = *(const uint2*)(xh + (size_t)e0.x * 64 + lane * 2);
        float c0 = __int_as_float(e0.y);
        float2 f00 = __half22float2(*(__half2*)&r0.x), f01 = __half22float2(*(__half2*)&r0.y);
        a0.x += c0 * f00.x; a0.y += c0 * f00.y; a0.z += c0 * f01.x; a0.w += c0 * f01.y;
    }
    a0.x += a1.x; a0.y += a1.y; a0.z += a1.z; a0.w += a1.w;
    float d2 = g_dis[node]; d2 *= d2;
    uint2 rv = *(const uint2*)(xh + (size_t)node * 64 + lane * 2);
    float2 v0 = __half22float2(*(__half2*)&rv.x), v1 = __half22float2(*(__half2*)&rv.y);
    float4 b = *(const float4*)&bias[lane * 4];
    a0.x += d2 * v0.x + b.x; a0.y += d2 * v0.y + b.y;
    a0.z += d2 * v1.x + b.z; a0.w += d2 * v1.y + b.w;
    if (RELU) {
        a0.x = fmaxf(a0.x, 0.f); a0.y = fmaxf(a0.y, 0.f);
        a0.z = fmaxf(a0.z, 0.f); a0.w = fmaxf(a0.w, 0.f);
    }
    if (OUT_H) {
        __half2* dst = (__half2*)&outh[(size_t)node * EMB_DIM + lane * 4];
        dst[0] = __floats2half2_rn(a0.x, a0.y);
        dst[1] = __floats2half2_rn(a0.z, a0.w);
    } else {
        *(float4*)&outf[(size_t)node * EMB_DIM + lane * 4] = a0;
    }
}

// node GEMM: [N_NODES,128](half) x W[128,128]^T -> half g_XWh
__global__ void __launch_bounds__(256) k_hgemm_node(const __half* __restrict__ A,
                                                    const float* __restrict__ W) {
    hgemm<false, true>(A, EMB_DIM, W, EMB_DIM, nullptr, 0, g_XWh,
                       blockIdx.y * 64, 0, 0, EMB_DIM, N_NODES);
}

__global__ void __launch_bounds__(512) k_pool_seg(const float* __restrict__ xg) {
    __shared__ float sh[512];
    int g = blockIdx.x;
    int d = threadIdx.x & 127, l4 = threadIdx.x >> 7;
    int s = g_goff[g], e = g_goff[g + 1];
    float acc = 0.f;
    for (int i = s + l4; i < e; i += 4) acc += xg[(size_t)i * EMB_DIM + d];
    sh[threadIdx.x] = acc;
    __syncthreads();
    if (threadIdx.x < 128) {
        float v = sh[d] + sh[128 + d] + sh[256 + d] + sh[384 + d];
        float c = fmaxf((float)(e - s), 1.f);
        g_xc[g * CAT_DIM + IMG_DIM + d] = v / c;
    }
}

// ---------------- fp32 SIMT 64x64 SGEMM (heads) ----------------------------------
__device__ __forceinline__ void sgemm64(const float* __restrict__ A, int lda,
                                        const float* __restrict__ B, int ldb,
                                        float* __restrict__ C, int ldc,
                                        int m0, int n0, int k0, int klen,
                                        int M, int N) {
    __shared__ float As[16][68];
    __shared__ float Bs[16][68];
    int t = threadIdx.x;
    int tn = t & 15, tm = t >> 4;
    int lrow = t >> 2, lkq = (t & 3) << 2;

    float c[4][4];
    #pragma unroll
    for (int i = 0; i < 4; i++)
        #pragma unroll
        for (int j = 0; j < 4; j++) c[i][j] = 0.f;

    for (int kk = k0; kk < k0 + klen; kk += 16) {
        float4 a;
        int am = m0 + lrow;
        if (am < M) a = *(const float4*)&A[(size_t)am * lda + kk + lkq];
        else        a = make_float4(0.f, 0.f, 0.f, 0.f);
        As[lkq + 0][lrow] = a.x; As[lkq + 1][lrow] = a.y;
        As[lkq + 2][lrow] = a.z; As[lkq + 3][lrow] = a.w;
        int bn = n0 + lrow;
        float4 b;
        if (bn < N) b = *(const float4*)&B[(size_t)bn * ldb + kk + lkq];
        else        b = make_float4(0.f, 0.f, 0.f, 0.f);
        Bs[lkq + 0][lrow] = b.x; Bs[lkq + 1][lrow] = b.y;
        Bs[lkq + 2][lrow] = b.z; Bs[lkq + 3][lrow] = b.w;
        __syncthreads();
        #pragma unroll
        for (int k = 0; k < 16; k++) {
            float4 af = *(const float4*)&As[k][tm * 4];
            float4 bf = *(const float4*)&Bs[k][tn * 4];
            c[0][0] += af.x * bf.x; c[0][1] += af.x * bf.y; c[0][2] += af.x * bf.z; c[0][3] += af.x * bf.w;
            c[1][0] += af.y * bf.x; c[1][1] += af.y * bf.y; c[1][2] += af.y * bf.z; c[1][3] += af.y * bf.w;
            c[2][0] += af.z * bf.x; c[2][1] += af.z * bf.y; c[2][2] += af.z * bf.z; c[2][3] += af.z * bf.w;
            c[3][0] += af.w * bf.x; c[3][1] += af.w * bf.y; c[3][2] += af.w * bf.z; c[3][3] += af.w * bf.w;
        }
        __syncthreads();
    }
    #pragma unroll
    for (int i = 0; i < 4; i++) {
        int m = m0 + tm * 4 + i;
        if (m >= M) continue;
        #pragma unroll
        for (int j = 0; j < 4; j++)
            C[(size_t)m * ldc + n0 + tn * 4 + j] = c[i][j];
    }
}

// both heads, one launch: z<HI_SPLITS -> oi partials, else oc partials
__global__ void __launch_bounds__(256) k_heads(const float* __restrict__ xc,
                                               const float* __restrict__ Wi,
                                               const float* __restrict__ Wc) {
    int z = blockIdx.z;
    if (z < HI_SPLITS) {
        sgemm64(xc, CAT_DIM, Wi, IMG_DIM, g_hpi + (size_t)z * 64 * EMB_DIM, EMB_DIM,
                0, blockIdx.x * 64, z * HEAD_KC, HEAD_KC, 64, EMB_DIM);
    } else {
        int z2 = z - HI_SPLITS;
        sgemm64(xc, CAT_DIM, Wc, CAT_DIM, g_hpc + (size_t)z2 * 64 * EMB_DIM, EMB_DIM,
                0, blockIdx.x * 64, z2 * HEAD_KC, HEAD_KC, 64, EMB_DIM);
    }
}

__global__ void k_headnorm(const float* __restrict__ bi, const float* __restrict__ bc,
                           float* __restrict__ out) {
    __shared__ float sh[4];
    int which = blockIdx.x >> 6, m = blockIdx.x & 63, n = threadIdx.x;
    float v;
    if (which == 0) {
        v = bi[n];
        #pragma unroll
        for (int z = 0; z < HI_SPLITS; z++) v += g_hpi[(z * 64 + m) * EMB_DIM + n];
    } else {
        v = bc[n];
        #pragma unroll
        for (int z = 0; z < HC_SPLITS; z++) v += g_hpc[(z * 64 + m) * EMB_DIM + n];
    }
    float s = v * v;
    #pragma unroll
    for (int o = 16; o; o >>= 1) s += __shfl_xor_sync(0xffffffffu, s, o);
    if ((n & 31) == 0) sh[n >> 5] = s;
    __syncthreads();
    float tot = sh[0] + sh[1] + sh[2] + sh[3];
    out[blockIdx.x * EMB_DIM + n] = v * rsqrtf(tot);
}

// ---------------- host ----------------------------------------------------------
extern "C" void kernel_launch(void* const* d_in, const int* in_sizes, int n_in,
                              void* d_out, int out_size) {
    const float* images = (const float*)d_in[0];
    const int*   ntypes = (const int*)  d_in[1];
    const int*   eidx   = (const int*)  d_in[2];
    const float* eattr  = (const float*)d_in[3];
    const int*   batch  = (const int*)  d_in[4];
    const float* emb    = (const float*)d_in[5];
    const float* W_img  = (const float*)d_in[6];
    const float* b_img  = (const float*)d_in[7];
    const float* W1     = (const float*)d_in[8];
    const float* b1     = (const float*)d_in[9];
    const float* W2     = (const float*)d_in[10];
    const float* b2     = (const float*)d_in[11];
    const float* W3     = (const float*)d_in[12];
    const float* b3     = (const float*)d_in[13];
    const float* Wi     = (const float*)d_in[14];
    const float* bi     = (const float*)d_in[15];
    const float* Wc     = (const float*)d_in[16];
    const float* bc     = (const float*)d_in[17];
    float* out = (float*)d_out;

    __half *p_bufAh, *p_bufBh;
    float *p_bufC, *p_xc;
    cudaGetSymbolAddress((void**)&p_bufAh, g_bufAh);
    cudaGetSymbolAddress((void**)&p_bufBh, g_bufBh);
    cudaGetSymbolAddress((void**)&p_bufC,  g_bufC);
    cudaGetSymbolAddress((void**)&p_xc,    g_xc);

    const int T = 256;
    int nb_nodes = (N_NODES + T - 1) / T;
    int nb_edges = (N_EDGES + T - 1) / T;

    // preprocessing (table GEMM fused into init)
    k_init_table<<<15 + nb_nodes, T>>>(emb, W1);
    k_deg<<<nb_edges, T>>>(eidx, eattr, batch);
    k_scan<<<1, 1024>>>();

    // image GEMM (pipelined) + edge scatter in one launch
    k_big<<<IMG_BLOCKS + nb_edges, T>>>(images, W_img, eidx, eattr, ntypes);

    // image reduce + layer-1 agg (half table, HFMA2) in one launch
    k_fused2<<<IRED_BLOCKS + AGG_BLOCKS, T>>>(b_img, b1, ntypes);

    // layer 2 (HMMA) + agg
    k_hgemm_node<<<dim3(1, (N_NODES + 63) / 64), T>>>(p_bufAh, W2);
    k_agg<true, true><<<AGG_BLOCKS, T>>>(b2, p_bufBh, nullptr);

    // layer 3 (HMMA) + agg (fp32 out)
    k_hgemm_node<<<dim3(1, (N_NODES + 63) / 64), T>>>(p_bufBh, W3);
    k_agg<false, false><<<AGG_BLOCKS, T>>>(b3, nullptr, p_bufC);

    // pooling -> g_xc[:, 4096:]
    k_pool_seg<<<N_GRAPHS, 512>>>(p_bufC);

    // heads (one launch) + fused reduce/normalize
    k_heads<<<dim3(2, 1, HI_SPLITS + HC_SPLITS), T>>>(p_xc, Wi, Wc);
    k_headnorm<<<2 * 64, EMB_DIM>>>(bi, bc, out);

    (void)in_sizes; (void)n_in; (void)out_size;
}

// round 16
// speedup vs baseline: 1.0927x; 1.0540x over previous
#include <cuda_runtime.h>
#include <cuda_fp16.h>

typedef unsigned int uint;

#define N_NODES 50000
#define N_EDGES 800000
#define N_GRAPHS 64
#define EMB_DIM 128
#define IMG_DIM 4096
#define N_TYPES 30
#define CAT_DIM (IMG_DIM + EMB_DIM)   // 4224

#define IMG_SPLITS 8
#define IMG_KC 512                    // 4096/8
#define IMG_NTILES 32                 // 4096/128
#define IMG_BLOCKS (IMG_SPLITS * IMG_NTILES)  // 256
#define HEAD_KC 128
#define HI_SPLITS 32
#define HC_SPLITS 33
#define AGG_BLOCKS ((N_NODES + 7) / 8)
#define IRED_BLOCKS (64 * IMG_DIM / 256)      // 1024

// ---------------- device scratch ------------------------------------------------
__device__ float g_dis[N_NODES];
__device__ int   g_cnt_e[N_NODES];
__device__ int   g_offs[N_NODES + 1];
__device__ int   g_cursor[N_NODES];
__device__ int2  g_epack[N_EDGES];            // (row, coef) for layers 2/3
__device__ int2  g_tpack[N_EDGES];            // (type[row], coef) for layer 1
__device__ int   g_goff[N_GRAPHS + 1];

__device__ __half g_XWh[N_NODES * EMB_DIM];   // node GEMM out / agg in (half)
__device__ __half g_bufAh[N_NODES * EMB_DIM]; // agg1 out (half, relu)
__device__ __half g_bufBh[N_NODES * EMB_DIM]; // agg2 out (half, relu)
__device__ float  g_bufC[N_NODES * EMB_DIM];  // agg3 out (fp32)
__device__ __half g_TXWh[N_TYPES * EMB_DIM];
__device__ float  g_xc[N_GRAPHS * CAT_DIM];   // [xi | pooled]
__device__ float  g_ipart[IMG_SPLITS * 64 * IMG_DIM];
__device__ float  g_hpi[HI_SPLITS * 64 * EMB_DIM];
__device__ float  g_hpc[HC_SPLITS * 64 * EMB_DIM];

// ---------------- init + layer-1 table GEMM (fused) -----------------------------
__global__ void k_init_table(const float* __restrict__ emb, const float* __restrict__ W1) {
    if (blockIdx.x < 15) {
        __shared__ float xr[2][EMB_DIM];
        int sub = threadIdx.x >> 7;
        int d = threadIdx.x & 127;
        int t = blockIdx.x * 2 + sub;
        xr[sub][d] = emb[t * EMB_DIM + d];
        __syncthreads();
        const float* w = &W1[d * EMB_DIM];
        const float* x = xr[sub];
        float s = 0.f;
        #pragma unroll 8
        for (int k = 0; k < EMB_DIM; k++) s += x[k] * w[k];
        g_TXWh[t * EMB_DIM + d] = __float2half(s);
    } else {
        int i = (blockIdx.x - 15) * blockDim.x + threadIdx.x;
        if (i < N_NODES) { g_dis[i] = 1.0f; g_cnt_e[i] = 0; g_cursor[i] = 0; }
    }
}

__global__ void k_deg(const int* __restrict__ ei, const float* __restrict__ ea,
                      const int* __restrict__ batch) {
    int i = blockIdx.x * blockDim.x + threadIdx.x;
    if (i < N_EDGES) {
        int c = ei[N_EDGES + i];
        atomicAdd(&g_dis[c], ea[i]);
        atomicAdd(&g_cnt_e[c], 1);
    }
    if (i < N_NODES) {
        int b = batch[i];
        if (i == 0) {
            for (int g = 0; g <= b; g++) g_goff[g] = 0;
        } else {
            int pb = batch[i - 1];
            for (int g = pb + 1; g <= b; g++) g_goff[g] = i;
        }
        if (i == N_NODES - 1)
            for (int g = b + 1; g <= N_GRAPHS; g++) g_goff[g] = N_NODES;
    }
}

__global__ void k_scan() {
    __shared__ int sh[1024];
    const int C = (N_NODES + 1023) / 1024;
    int t = threadIdx.x;
    int base = t * C;
    int sum = 0;
    for (int j = 0; j < C; j++) { int i = base + j; if (i < N_NODES) sum += g_cnt_e[i]; }
    sh[t] = sum;
    __syncthreads();
    for (int off = 1; off < 1024; off <<= 1) {
        int v = (t >= off) ? sh[t - off] : 0;
        __syncthreads();
        sh[t] += v;
        __syncthreads();
    }
    int prefix = t ? sh[t - 1] : 0;
    for (int j = 0; j < C; j++) {
        int i = base + j;
        if (i < N_NODES) { int c = g_cnt_e[i]; g_offs[i] = prefix; prefix += c; }
    }
    if (t == 1023) g_offs[N_NODES] = sh[1023];
    for (int i = t; i < N_NODES; i += 1024) g_dis[i] = rsqrtf(g_dis[i]);
}

// ---------------- HMMA GEMM building block ---------------------------------------
__device__ __forceinline__ void mma16816(float* c, uint a0, uint a1, uint a2, uint a3,
                                         uint b0, uint b1) {
    asm volatile("mma.sync.aligned.m16n8k16.row.col.f32.f16.f16.f32 "
                 "{%0,%1,%2,%3}, {%4,%5,%6,%7}, {%8,%9}, {%0,%1,%2,%3};"
                 : "+f"(c[0]), "+f"(c[1]), "+f"(c[2]), "+f"(c[3])
                 : "r"(a0), "r"(a1), "r"(a2), "r"(a3), "r"(b0), "r"(b1));
}

// block tile 64(M) x 128(N), k-chunk 64; 8 warps = 4(M) x 2(N).
// Register double-buffered global loads.
template <bool CONV_A, bool OUT_HALF>
__device__ __forceinline__ void hgemm(const void* Av, int lda,
                                      const float* __restrict__ B, int ldb,
                                      float* __restrict__ C, int ldc,
                                      __half* __restrict__ Ch,
                                      int m0, int n0, int k0, int klen, int M) {
    __shared__ __half As[64][72];
    __shared__ __half Bs[128][72];
    int t = threadIdx.x;
    int w = t >> 5, l = t & 31;
    int g = l >> 2, tig = l & 3;
    int m_off = (w & 3) * 16, n_off = (w >> 2) * 64;

    float acc[8][4];
    #pragma unroll
    for (int nf = 0; nf < 8; nf++)
        #pragma unroll
        for (int j = 0; j < 4; j++) acc[nf][j] = 0.f;

    float4 ra[4];
    uint4  rah[2];
    float4 rb[8];

    const int nk = klen >> 6;

    {
        int kc = k0;
        if (CONV_A) {
            const float* A = (const float*)Av;
            #pragma unroll
            for (int i = 0; i < 4; i++) {
                int idx = t + i * 256;
                int r = idx >> 4, c4 = (idx & 15) << 2;
                int am = m0 + r;
                ra[i] = (am < M) ? *(const float4*)&A[(size_t)am * lda + kc + c4]
                                 : make_float4(0.f, 0.f, 0.f, 0.f);
            }
        } else {
            const __half* A = (const __half*)Av;
            #pragma unroll
            for (int i = 0; i < 2; i++) {
                int idx = t + i * 256;
                int r = idx >> 3, c8 = (idx & 7) << 3;
                int am = m0 + r;
                rah[i] = (am < M) ? *(const uint4*)&A[(size_t)am * lda + kc + c8]
                                  : make_uint4(0u, 0u, 0u, 0u);
            }
        }
        #pragma unroll
        for (int i = 0; i < 8; i++) {
            int idx = t + i * 256;
            int r = idx >> 4, c4 = (idx & 15) << 2;
            rb[i] = *(const float4*)&B[(size_t)(n0 + r) * ldb + kc + c4];
        }
    }

    for (int it = 0; it < nk; it++) {
        if (CONV_A) {
            #pragma unroll
            for (int i = 0; i < 4; i++) {
                int idx = t + i * 256;
                int r = idx >> 4, c4 = (idx & 15) << 2;
                __half2* d = (__half2*)&As[r][c4];
                d[0] = __floats2half2_rn(ra[i].x, ra[i].y);
                d[1] = __floats2half2_rn(ra[i].z, ra[i].w);
            }
        } else {
            #pragma unroll
            for (int i = 0; i < 2; i++) {
                int idx = t + i * 256;
                int r = idx >> 3, c8 = (idx & 7) << 3;
                *(uint4*)&As[r][c8] = rah[i];
            }
        }
        #pragma unroll
        for (int i = 0; i < 8; i++) {
            int idx = t + i * 256;
            int r = idx >> 4, c4 = (idx & 15) << 2;
            __half2* d = (__half2*)&Bs[r][c4];
            d[0] = __floats2half2_rn(rb[i].x, rb[i].y);
            d[1] = __floats2half2_rn(rb[i].z, rb[i].w);
        }
        __syncthreads();

        if (it + 1 < nk) {
            int kc = k0 + (it + 1) * 64;
            if (CONV_A) {
                const float* A = (const float*)Av;
                #pragma unroll
                for (int i = 0; i < 4; i++) {
                    int idx = t + i * 256;
                    int r = idx >> 4, c4 = (idx & 15) << 2;
                    int am = m0 + r;
                    ra[i] = (am < M) ? *(const float4*)&A[(size_t)am * lda + kc + c4]
                                     : make_float4(0.f, 0.f, 0.f, 0.f);
                }
            } else {
                const __half* A = (const __half*)Av;
                #pragma unroll
                for (int i = 0; i < 2; i++) {
                    int idx = t + i * 256;
                    int r = idx >> 3, c8 = (idx & 7) << 3;
                    int am = m0 + r;
                    rah[i] = (am < M) ? *(const uint4*)&A[(size_t)am * lda + kc + c8]
                                      : make_uint4(0u, 0u, 0u, 0u);
                }
            }
            #pragma unroll
            for (int i = 0; i < 8; i++) {
                int idx = t + i * 256;
                int r = idx >> 4, c4 = (idx & 15) << 2;
                rb[i] = *(const float4*)&B[(size_t)(n0 + r) * ldb + kc + c4];
            }
        }

        #pragma unroll
        for (int ks = 0; ks < 4; ks++) {
            int kk = ks * 16 + 2 * tig;
            uint a0 = *(const uint*)&As[m_off + g][kk];
            uint a1 = *(const uint*)&As[m_off + g + 8][kk];
            uint a2 = *(const uint*)&As[m_off + g][kk + 8];
            uint a3 = *(const uint*)&As[m_off + g + 8][kk + 8];
            #pragma unroll
            for (int nf = 0; nf < 8; nf++) {
                uint b0 = *(const uint*)&Bs[n_off + nf * 8 + g][kk];
                uint b1 = *(const uint*)&Bs[n_off + nf * 8 + g][kk + 8];
                mma16816(acc[nf], a0, a1, a2, a3, b0, b1);
            }
        }
        __syncthreads();
    }

    #pragma unroll
    for (int nf = 0; nf < 8; nf++) {
        int col = n0 + n_off + nf * 8 + 2 * tig;
        int m1 = m0 + m_off + g, m2 = m1 + 8;
        if (OUT_HALF) {
            if (m1 < M) *(__half2*)&Ch[(size_t)m1 * EMB_DIM + col] = __floats2half2_rn(acc[nf][0], acc[nf][1]);
            if (m2 < M) *(__half2*)&Ch[(size_t)m2 * EMB_DIM + col] = __floats2half2_rn(acc[nf][2], acc[nf][3]);
        } else {
            if (m1 < M) { C[(size_t)m1 * ldc + col] = acc[nf][0]; C[(size_t)m1 * ldc + col + 1] = acc[nf][1]; }
            if (m2 < M) { C[(size_t)m2 * ldc + col] = acc[nf][2]; C[(size_t)m2 * ldc + col + 1] = acc[nf][3]; }
        }
    }
}

// ---------------- big fused kernel: image HMMA GEMM + edge scatter ---------------
__global__ void __launch_bounds__(256) k_big(const float* __restrict__ images,
                                             const float* __restrict__ W_img,
                                             const int* __restrict__ ei,
                                             const float* __restrict__ ea,
                                             const int* __restrict__ types) {
    if (blockIdx.x < IMG_BLOCKS) {
        int ntile = blockIdx.x & (IMG_NTILES - 1), z = blockIdx.x / IMG_NTILES;
        hgemm<true, false>(images, IMG_DIM, W_img, IMG_DIM,
                           g_ipart + (size_t)z * 64 * IMG_DIM, IMG_DIM, nullptr,
                           0, ntile * 128, z * IMG_KC, IMG_KC, 64);
    } else {
        int e = (blockIdx.x - IMG_BLOCKS) * 256 + threadIdx.x;
        if (e < N_EDGES) {
            int r = ei[e], c = ei[N_EDGES + e];
            float coef = g_dis[r] * ea[e] * g_dis[c];
            int pos = g_offs[c] + atomicAdd(&g_cursor[c], 1);
            int ci = __float_as_int(coef);
            g_epack[pos] = make_int2(r, ci);
            g_tpack[pos] = make_int2(types[r], ci);
        }
    }
}

// ---------------- layer-1 agg (half smem table, HFMA2) + image reduce ------------
__global__ void __launch_bounds__(256) k_fused2(const float* __restrict__ b_img,
                                                const float* __restrict__ b1,
                                                const int* __restrict__ types) {
    if (blockIdx.x < IRED_BLOCKS) {
        int i = blockIdx.x * 256 + threadIdx.x;
        int m = i >> 12, n = i & (IMG_DIM - 1);
        float v = b_img[n];
        #pragma unroll
        for (int z = 0; z < IMG_SPLITS; z++)
            v += g_ipart[((size_t)z * 64 + m) * IMG_DIM + n];
        g_xc[m * CAT_DIM + n] = v;
        return;
    }
    __shared__ uint sT[N_TYPES * 64];   // 30 rows x 64 half2
    for (int i = threadIdx.x; i < N_TYPES * 64; i += 256)
        sT[i] = ((const uint*)g_TXWh)[i];
    __syncthreads();

    int bid = blockIdx.x - IRED_BLOCKS;
    int node = bid * 8 + ((int)threadIdx.x >> 5);
    if (node >= N_NODES) return;
    int lane = threadIdx.x & 31;
    int s = g_offs[node], e = g_offs[node + 1];

    __half2 z2 = __floats2half2_rn(0.f, 0.f);
    __half2 a00 = z2, a01 = z2;
    __half2 a10 = z2, a11 = z2;
    int p = s;
    for (; p + 1 < e; p += 2) {
        int2 e0 = g_tpack[p], e1 = g_tpack[p + 1];
        uint2 r0 = *(const uint2*)&sT[e0.x * 64 + lane * 2];
        uint2 r1 = *(const uint2*)&sT[e1.x * 64 + lane * 2];
        __half2 c0 = __float2half2_rn(__int_as_float(e0.y));
        __half2 c1 = __float2half2_rn(__int_as_float(e1.y));
        a00 = __hfma2(*(__half2*)&r0.x, c0, a00);
        a01 = __hfma2(*(__half2*)&r0.y, c0, a01);
        a10 = __hfma2(*(__half2*)&r1.x, c1, a10);
        a11 = __hfma2(*(__half2*)&r1.y, c1, a11);
    }
    if (p < e) {
        int2 e0 = g_tpack[p];
        uint2 r0 = *(const uint2*)&sT[e0.x * 64 + lane * 2];
        __half2 c0 = __float2half2_rn(__int_as_float(e0.y));
        a00 = __hfma2(*(__half2*)&r0.x, c0, a00);
        a01 = __hfma2(*(__half2*)&r0.y, c0, a01);
    }
    float2 f0 = __half22float2(a00), f0b = __half22float2(a10);
    float2 f1 = __half22float2(a01), f1b = __half22float2(a11);
    float4 acc = make_float4(f0.x + f0b.x, f0.y + f0b.y, f1.x + f1b.x, f1.y + f1b.y);
    float d2 = g_dis[node]; d2 *= d2;
    int ts = types[node];
    uint2 rv = *(const uint2*)&sT[ts * 64 + lane * 2];
    float2 v0 = __half22float2(*(__half2*)&rv.x), v1 = __half22float2(*(__half2*)&rv.y);
    float4 b = *(const float4*)&b1[lane * 4];
    acc.x += d2 * v0.x + b.x; acc.y += d2 * v0.y + b.y;
    acc.z += d2 * v1.x + b.z; acc.w += d2 * v1.y + b.w;
    acc.x = fmaxf(acc.x, 0.f); acc.y = fmaxf(acc.y, 0.f);
    acc.z = fmaxf(acc.z, 0.f); acc.w = fmaxf(acc.w, 0.f);
    __half2* dst = (__half2*)&g_bufAh[(size_t)node * EMB_DIM + lane * 4];
    dst[0] = __floats2half2_rn(acc.x, acc.y);
    dst[1] = __floats2half2_rn(acc.z, acc.w);
}

// ---------------- CSR aggregation layers 2/3: 4-edge unroll + HFMA2 --------------
template <bool RELU, bool OUT_H>
__global__ void __launch_bounds__(256) k_agg(const float* __restrict__ bias,
                                             __half* __restrict__ outh,
                                             float* __restrict__ outf) {
    int node = blockIdx.x * 8 + ((int)threadIdx.x >> 5);
    if (node >= N_NODES) return;
    int lane = threadIdx.x & 31;
    const __half2* xh = (const __half2*)g_XWh;
    int s = g_offs[node], e = g_offs[node + 1];

    __half2 z2 = __floats2half2_rn(0.f, 0.f);
    __half2 a00 = z2, a01 = z2;   // chain 0
    __half2 a10 = z2, a11 = z2;   // chain 1
    __half2 a20 = z2, a21 = z2;   // chain 2
    __half2 a30 = z2, a31 = z2;   // chain 3
    int p = s;
    for (; p + 3 < e; p += 4) {
        int2 e0 = g_epack[p],     e1 = g_epack[p + 1];
        int2 e2 = g_epack[p + 2], e3 = g_epack[p + 3];
        uint2 r0 = *(const uint2*)(xh + (size_t)e0.x * 64 + lane * 2);
        uint2 r1 = *(const uint2*)(xh + (size_t)e1.x * 64 + lane * 2);
        uint2 r2 = *(const uint2*)(xh + (size_t)e2.x * 64 + lane * 2);
        uint2 r3 = *(const uint2*)(xh + (size_t)e3.x * 64 + lane * 2);
        __half2 c0 = __float2half2_rn(__int_as_float(e0.y));
        __half2 c1 = __float2half2_rn(__int_as_float(e1.y));
        __half2 c2 = __float2half2_rn(__int_as_float(e2.y));
        __half2 c3 = __float2half2_rn(__int_as_float(e3.y));
        a00 = __hfma2(*(__half2*)&r0.x, c0, a00);
        a01 = __hfma2(*(__half2*)&r0.y, c0, a01);
        a10 = __hfma2(*(__half2*)&r1.x, c1, a10);
        a11 = __hfma2(*(__half2*)&r1.y, c1, a11);
        a20 = __hfma2(*(__half2*)&r2.x, c2, a20);
        a21 = __hfma2(*(__half2*)&r2.y, c2, a21);
        a30 = __hfma2(*(__half2*)&r3.x, c3, a30);
        a31 = __hfma2(*(__half2*)&r3.y, c3, a31);
    }
    for (; p < e; p++) {
        int2 e0 = g_epack[p];
        uint2 r0 = *(const uint2*)(xh + (size_t)e0.x * 64 + lane * 2);
        __half2 c0 = __float2half2_rn(__int_as_float(e0.y));
        a00 = __hfma2(*(__half2*)&r0.x, c0, a00);
        a01 = __hfma2(*(__half2*)&r0.y, c0, a01);
    }
    // combine 4 chains in fp32
    float2 f00 = __half22float2(a00), f10 = __half22float2(a10);
    float2 f20 = __half22float2(a20), f30 = __half22float2(a30);
    float2 f01 = __half22float2(a01), f11 = __half22float2(a11);
    float2 f21 = __half22float2(a21), f31 = __half22float2(a31);
    float4 acc = make_float4((f00.x + f10.x) + (f20.x + f30.x),
                             (f00.y + f10.y) + (f20.y + f30.y),
                             (f01.x + f11.x) + (f21.x + f31.x),
                             (f01.y + f11.y) + (f21.y + f31.y));
    float d2 = g_dis[node]; d2 *= d2;
    uint2 rv = *(const uint2*)(xh + (size_t)node * 64 + lane * 2);
    float2 v0 = __half22float2(*(__half2*)&rv.x), v1 = __half22float2(*(__half2*)&rv.y);
    float4 b = *(const float4*)&bias[lane * 4];
    acc.x += d2 * v0.x + b.x; acc.y += d2 * v0.y + b.y;
    acc.z += d2 * v1.x + b.z; acc.w += d2 * v1.y + b.w;
    if (RELU) {
        acc.x = fmaxf(acc.x, 0.f); acc.y = fmaxf(acc.y, 0.f);
        acc.z = fmaxf(acc.z, 0.f); acc.w = fmaxf(acc.w, 0.f);
    }
    if (OUT_H) {
        __half2* dst = (__half2*)&outh[(size_t)node * EMB_DIM + lane * 4];
        dst[0] = __floats2half2_rn(acc.x, acc.y);
        dst[1] = __floats2half2_rn(acc.z, acc.w);
    } else {
        *(float4*)&outf[(size_t)node * EMB_DIM + lane * 4] = acc;
    }
}

// node GEMM: [N_NODES,128](half) x W[128,128]^T -> half g_XWh
__global__ void __launch_bounds__(256) k_hgemm_node(const __half* __restrict__ A,
                                                    const float* __restrict__ W) {
    hgemm<false, true>(A, EMB_DIM, W, EMB_DIM, nullptr, 0, g_XWh,
                       blockIdx.y * 64, 0, 0, EMB_DIM, N_NODES);
}

__global__ void __launch_bounds__(512) k_pool_seg(const float* __restrict__ xg) {
    __shared__ float sh[512];
    int g = blockIdx.x;
    int d = threadIdx.x & 127, l4 = threadIdx.x >> 7;
    int s = g_goff[g], e = g_goff[g + 1];
    float acc = 0.f;
    for (int i = s + l4; i < e; i += 4) acc += xg[(size_t)i * EMB_DIM + d];
    sh[threadIdx.x] = acc;
    __syncthreads();
    if (threadIdx.x < 128) {
        float v = sh[d] + sh[128 + d] + sh[256 + d] + sh[384 + d];
        float c = fmaxf((float)(e - s), 1.f);
        g_xc[g * CAT_DIM + IMG_DIM + d] = v / c;
    }
}

// ---------------- fp32 SIMT 64x64 SGEMM (heads) ----------------------------------
__device__ __forceinline__ void sgemm64(const float* __restrict__ A, int lda,
                                        const float* __restrict__ B, int ldb,
                                        float* __restrict__ C, int ldc,
                                        int m0, int n0, int k0, int klen,
                                        int M, int N) {
    __shared__ float As[16][68];
    __shared__ float Bs[16][68];
    int t = threadIdx.x;
    int tn = t & 15, tm = t >> 4;
    int lrow = t >> 2, lkq = (t & 3) << 2;

    float c[4][4];
    #pragma unroll
    for (int i = 0; i < 4; i++)
        #pragma unroll
        for (int j = 0; j < 4; j++) c[i][j] = 0.f;

    for (int kk = k0; kk < k0 + klen; kk += 16) {
        float4 a;
        int am = m0 + lrow;
        if (am < M) a = *(const float4*)&A[(size_t)am * lda + kk + lkq];
        else        a = make_float4(0.f, 0.f, 0.f, 0.f);
        As[lkq + 0][lrow] = a.x; As[lkq + 1][lrow] = a.y;
        As[lkq + 2][lrow] = a.z; As[lkq + 3][lrow] = a.w;
        int bn = n0 + lrow;
        float4 b;
        if (bn < N) b = *(const float4*)&B[(size_t)bn * ldb + kk + lkq];
        else        b = make_float4(0.f, 0.f, 0.f, 0.f);
        Bs[lkq + 0][lrow] = b.x; Bs[lkq + 1][lrow] = b.y;
        Bs[lkq + 2][lrow] = b.z; Bs[lkq + 3][lrow] = b.w;
        __syncthreads();
        #pragma unroll
        for (int k = 0; k < 16; k++) {
            float4 af = *(const float4*)&As[k][tm * 4];
            float4 bf = *(const float4*)&Bs[k][tn * 4];
            c[0][0] += af.x * bf.x; c[0][1] += af.x * bf.y; c[0][2] += af.x * bf.z; c[0][3] += af.x * bf.w;
            c[1][0] += af.y * bf.x; c[1][1] += af.y * bf.y; c[1][2] += af.y * bf.z; c[1][3] += af.y * bf.w;
            c[2][0] += af.z * bf.x; c[2][1] += af.z * bf.y; c[2][2] += af.z * bf.z; c[2][3] += af.z * bf.w;
            c[3][0] += af.w * bf.x; c[3][1] += af.w * bf.y; c[3][2] += af.w * bf.z; c[3][3] += af.w * bf.w;
        }
        __syncthreads();
    }
    #pragma unroll
    for (int i = 0; i < 4; i++) {
        int m = m0 + tm * 4 + i;
        if (m >= M) continue;
        #pragma unroll
        for (int j = 0; j < 4; j++)
            C[(size_t)m * ldc + n0 + tn * 4 + j] = c[i][j];
    }
}

// both heads, one launch: z<HI_SPLITS -> oi partials, else oc partials
__global__ void __launch_bounds__(256) k_heads(const float* __restrict__ xc,
                                               const float* __restrict__ Wi,
                                               const float* __restrict__ Wc) {
    int z = blockIdx.z;
    if (z < HI_SPLITS) {
        sgemm64(xc, CAT_DIM, Wi, IMG_DIM, g_hpi + (size_t)z * 64 * EMB_DIM, EMB_DIM,
                0, blockIdx.x * 64, z * HEAD_KC, HEAD_KC, 64, EMB_DIM);
    } else {
        int z2 = z - HI_SPLITS;
        sgemm64(xc, CAT_DIM, Wc, CAT_DIM, g_hpc + (size_t)z2 * 64 * EMB_DIM, EMB_DIM,
                0, blockIdx.x * 64, z2 * HEAD_KC, HEAD_KC, 64, EMB_DIM);
    }
}

__global__ void k_headnorm(const float* __restrict__ bi, const float* __restrict__ bc,
                           float* __restrict__ out) {
    __shared__ float sh[4];
    int which = blockIdx.x >> 6, m = blockIdx.x & 63, n = threadIdx.x;
    float v;
    if (which == 0) {
        v = bi[n];
        #pragma unroll
        for (int z = 0; z < HI_SPLITS; z++) v += g_hpi[(z * 64 + m) * EMB_DIM + n];
    } else {
        v = bc[n];
        #pragma unroll
        for (int z = 0; z < HC_SPLITS; z++) v += g_hpc[(z * 64 + m) * EMB_DIM + n];
    }
    float s = v * v;
    #pragma unroll
    for (int o = 16; o; o >>= 1) s += __shfl_xor_sync(0xffffffffu, s, o);
    if ((n & 31) == 0) sh[n >> 5] = s;
    __syncthreads();
    float tot = sh[0] + sh[1] + sh[2] + sh[3];
    out[blockIdx.x * EMB_DIM + n] = v * rsqrtf(tot);
}

// ---------------- host ----------------------------------------------------------
extern "C" void kernel_launch(void* const* d_in, const int* in_sizes, int n_in,
                              void* d_out, int out_size) {
    const float* images = (const float*)d_in[0];
    const int*   ntypes = (const int*)  d_in[1];
    const int*   eidx   = (const int*)  d_in[2];
    const float* eattr  = (const float*)d_in[3];
    const int*   batch  = (const int*)  d_in[4];
    const float* emb    = (const float*)d_in[5];
    const float* W_img  = (const float*)d_in[6];
    const float* b_img  = (const float*)d_in[7];
    const float* W1     = (const float*)d_in[8];
    const float* b1     = (const float*)d_in[9];
    const float* W2     = (const float*)d_in[10];
    const float* b2     = (const float*)d_in[11];
    const float* W3     = (const float*)d_in[12];
    const float* b3     = (const float*)d_in[13];
    const float* Wi     = (const float*)d_in[14];
    const float* bi     = (const float*)d_in[15];
    const float* Wc     = (const float*)d_in[16];
    const float* bc     = (const float*)d_in[17];
    float* out = (float*)d_out;

    __half *p_bufAh, *p_bufBh;
    float *p_bufC, *p_xc;
    cudaGetSymbolAddress((void**)&p_bufAh, g_bufAh);
    cudaGetSymbolAddress((void**)&p_bufBh, g_bufBh);
    cudaGetSymbolAddress((void**)&p_bufC,  g_bufC);
    cudaGetSymbolAddress((void**)&p_xc,    g_xc);

    const int T = 256;
    int nb_nodes = (N_NODES + T - 1) / T;
    int nb_edges = (N_EDGES + T - 1) / T;

    // preprocessing (table GEMM fused into init)
    k_init_table<<<15 + nb_nodes, T>>>(emb, W1);
    k_deg<<<nb_edges, T>>>(eidx, eattr, batch);
    k_scan<<<1, 1024>>>();

    // image GEMM (pipelined) + edge scatter in one launch
    k_big<<<IMG_BLOCKS + nb_edges, T>>>(images, W_img, eidx, eattr, ntypes);

    // image reduce + layer-1 agg (half table, HFMA2) in one launch
    k_fused2<<<IRED_BLOCKS + AGG_BLOCKS, T>>>(b_img, b1, ntypes);

    // layer 2 (HMMA) + agg (HFMA2, 4-edge unroll)
    k_hgemm_node<<<dim3(1, (N_NODES + 63) / 64), T>>>(p_bufAh, W2);
    k_agg<true, true><<<AGG_BLOCKS, T>>>(b2, p_bufBh, nullptr);

    // layer 3 (HMMA) + agg (fp32 out)
    k_hgemm_node<<<dim3(1, (N_NODES + 63) / 64), T>>>(p_bufBh, W3);
    k_agg<false, false><<<AGG_BLOCKS, T>>>(b3, nullptr, p_bufC);

    // pooling -> g_xc[:, 4096:]
    k_pool_seg<<<N_GRAPHS, 512>>>(p_bufC);

    // heads (one launch) + fused reduce/normalize
    k_heads<<<dim3(2, 1, HI_SPLITS + HC_SPLITS), T>>>(p_xc, Wi, Wc);
    k_headnorm<<<2 * 64, EMB_DIM>>>(bi, bc, out);

    (void)in_sizes; (void)n_in; (void)out_size;
}